// round 6
// baseline (speedup 1.0000x reference)
#include <cuda_runtime.h>
#include <cuda_bf16.h>
#include <cstdint>

// Problem constants (shape fixed by dataset: img [64, 3, 512, 512])
constexpr int NCH = 64 * 3;        // 192 channels
constexpr int P   = 512 * 512;     // 262144 pixels / channel
constexpr int NB  = 256;           // bins

// Scratch (no cudaMalloc allowed) — __device__ globals
__device__ int           g_hist[NCH * NB];          // lut_kernel re-zeroes each replay
__device__ float         g_lut [NCH * NB];
__device__ unsigned char g_u8  [(size_t)NCH * P];   // 50.3 MB packed bin scratch (fits L2)

// ---------------------------------------------------------------------------
// Kernel 1: histogram + quantize. grid = (HB, NCH), 256 threads (8 warps).
// Per-warp private shared histograms (R5 style, no cross-warp interference),
// 2 float4 loads in flight, packed uchar4 scratch store.
// Input read uses __ldcs (evict-first) so the 201MB stream does not evict the
// 50MB scratch being built in L2.
// ---------------------------------------------------------------------------
constexpr int HB = 32;  // blocks per channel

__global__ void hist_quant_kernel(const float* __restrict__ in) {
    __shared__ int sh[8 * NB];             // 8 KB: one 256-bin hist per warp
    const int c    = blockIdx.y;
    const int warp = threadIdx.x >> 5;
    int* const myh = &sh[warp * NB];

    for (int i = threadIdx.x; i < 8 * NB; i += blockDim.x) sh[i] = 0;
    __syncthreads();

    const float4* bi = reinterpret_cast<const float4*>(in + (size_t)c * P);
    unsigned int* bo = reinterpret_cast<unsigned int*>(g_u8 + (size_t)c * P);
    const int n = (P / 4) / HB;            // 2048 float4 per block
    const int start = blockIdx.x * n;

    for (int i = threadIdx.x; i < n; i += 2 * blockDim.x) {
        float4 a = __ldcs(&bi[start + i]);
        float4 b = __ldcs(&bi[start + i + blockDim.x]);
        int a0 = (int)a.x, a1 = (int)a.y, a2 = (int)a.z, a3 = (int)a.w;
        int b0 = (int)b.x, b1 = (int)b.y, b2 = (int)b.z, b3 = (int)b.w;
        bo[start + i] = (unsigned)a0 | ((unsigned)a1 << 8) |
                        ((unsigned)a2 << 16) | ((unsigned)a3 << 24);
        bo[start + i + blockDim.x] = (unsigned)b0 | ((unsigned)b1 << 8) |
                                     ((unsigned)b2 << 16) | ((unsigned)b3 << 24);
        atomicAdd(&myh[a0], 1);
        atomicAdd(&myh[a1], 1);
        atomicAdd(&myh[a2], 1);
        atomicAdd(&myh[a3], 1);
        atomicAdd(&myh[b0], 1);
        atomicAdd(&myh[b1], 1);
        atomicAdd(&myh[b2], 1);
        atomicAdd(&myh[b3], 1);
    }
    __syncthreads();

    // Reduce 8 warp-hists -> global
    {
        const int b = threadIdx.x;         // 256 threads == 256 bins
        int s = 0;
#pragma unroll
        for (int k = 0; k < 8; k++) s += sh[k * NB + b];
        if (s) atomicAdd(&g_hist[c * NB + b], s);
    }
}

// ---------------------------------------------------------------------------
// Kernel 2: build per-channel LUT (exact PIL integer math), then re-zero the
// histogram so the next graph replay starts clean.
//   step = (P - last_nonzero_val) / 255
//   lut[i] = step==0 ? i : clamp((cs[i-1] + step/2) / max(step,1), 0, 255)
// (step==0 passthrough folded into identity LUT — inputs are exact integers)
// ---------------------------------------------------------------------------
__global__ void lut_kernel() {
    const int c = blockIdx.x;
    const int i = threadIdx.x;

    __shared__ int h[NB];
    __shared__ int cs[NB];
    __shared__ int red[NB];

    const int hv = g_hist[c * NB + i];
    h[i]  = hv;
    cs[i] = hv;
    __syncthreads();

#pragma unroll
    for (int off = 1; off < NB; off <<= 1) {
        int v = (i >= off) ? cs[i - off] : 0;
        __syncthreads();
        cs[i] += v;
        __syncthreads();
    }

    red[i] = (hv != 0) ? i : -1;
    __syncthreads();
#pragma unroll
    for (int s = 128; s > 0; s >>= 1) {
        if (i < s) red[i] = max(red[i], red[i + s]);
        __syncthreads();
    }
    const int last_idx = red[0];
    const int last_val = h[last_idx];

    const int step = (P - last_val) / 255;
    const int safe = step > 0 ? step : 1;

    const int prev = (i == 0) ? 0 : cs[i - 1];
    int lv = (prev + step / 2) / safe;
    lv = min(max(lv, 0), 255);
    if (step == 0) lv = i;                 // passthrough as identity LUT
    g_lut[c * NB + i] = (float)lv;

    g_hist[c * NB + i] = 0;                // clean for next replay
}

// ---------------------------------------------------------------------------
// Kernel 3: apply LUT from u8 scratch. grid = (AB, NCH), 256 threads.
// 4 uint4 per thread (2 in flight) -> 16 float4 streaming stores.
// Scratch reads should be mostly L2 hits (50MB resident); __stcs on the
// 201MB output stream avoids evicting not-yet-read scratch.
// ---------------------------------------------------------------------------
constexpr int AB = 16;  // blocks per channel

__global__ void apply_kernel(float* __restrict__ out) {
    __shared__ float slut[NB];
    const int c = blockIdx.y;
    slut[threadIdx.x] = g_lut[c * NB + threadIdx.x];
    __syncthreads();

    const uint4* bi = reinterpret_cast<const uint4*>(g_u8 + (size_t)c * P);
    float4*      bo = reinterpret_cast<float4*>(out + (size_t)c * P);
    const int n = (P / 16) / AB;           // 1024 uint4 per block, 4 per thread
    const int start = blockIdx.x * n;

    for (int i = threadIdx.x; i < n; i += 2 * blockDim.x) {
        uint4 wa = bi[start + i];
        uint4 wb = bi[start + i + blockDim.x];

        float4 o;
        int ob;

        ob = (start + i) * 4;
        o.x = slut[ wa.x        & 255]; o.y = slut[(wa.x >>  8) & 255];
        o.z = slut[(wa.x >> 16) & 255]; o.w = slut[(wa.x >> 24)      ];
        __stcs(&bo[ob + 0], o);
        o.x = slut[ wa.y        & 255]; o.y = slut[(wa.y >>  8) & 255];
        o.z = slut[(wa.y >> 16) & 255]; o.w = slut[(wa.y >> 24)      ];
        __stcs(&bo[ob + 1], o);
        o.x = slut[ wa.z        & 255]; o.y = slut[(wa.z >>  8) & 255];
        o.z = slut[(wa.z >> 16) & 255]; o.w = slut[(wa.z >> 24)      ];
        __stcs(&bo[ob + 2], o);
        o.x = slut[ wa.w        & 255]; o.y = slut[(wa.w >>  8) & 255];
        o.z = slut[(wa.w >> 16) & 255]; o.w = slut[(wa.w >> 24)      ];
        __stcs(&bo[ob + 3], o);

        ob = (start + i + blockDim.x) * 4;
        o.x = slut[ wb.x        & 255]; o.y = slut[(wb.x >>  8) & 255];
        o.z = slut[(wb.x >> 16) & 255]; o.w = slut[(wb.x >> 24)      ];
        __stcs(&bo[ob + 0], o);
        o.x = slut[ wb.y        & 255]; o.y = slut[(wb.y >>  8) & 255];
        o.z = slut[(wb.y >> 16) & 255]; o.w = slut[(wb.y >> 24)      ];
        __stcs(&bo[ob + 1], o);
        o.x = slut[ wb.z        & 255]; o.y = slut[(wb.z >>  8) & 255];
        o.z = slut[(wb.z >> 16) & 255]; o.w = slut[(wb.z >> 24)      ];
        __stcs(&bo[ob + 2], o);
        o.x = slut[ wb.w        & 255]; o.y = slut[(wb.w >>  8) & 255];
        o.z = slut[(wb.w >> 16) & 255]; o.w = slut[(wb.w >> 24)      ];
        __stcs(&bo[ob + 3], o);
    }
}

// ---------------------------------------------------------------------------
extern "C" void kernel_launch(void* const* d_in, const int* in_sizes, int n_in,
                              void* d_out, int out_size) {
    const float* img = (const float*)d_in[0];
    float* out = (float*)d_out;

    hist_quant_kernel<<<dim3(HB, NCH), 256>>>(img);
    lut_kernel<<<NCH, 256>>>();
    apply_kernel<<<dim3(AB, NCH), 256>>>(out);
}

// round 7
// speedup vs baseline: 1.1850x; 1.1850x over previous
#include <cuda_runtime.h>
#include <cuda_bf16.h>
#include <cstdint>

// Problem constants (shape fixed by dataset: img [64, 3, 512, 512])
constexpr int NCH = 192;           // 64*3 channels
constexpr int P   = 262144;        // 512*512 pixels / channel
constexpr int NB  = 256;           // bins

// Pipeline structure
constexpr int GROUPS = 8;
constexpr int CPG    = NCH / GROUPS;   // 24 channels per group
constexpr int HPC    = 8;              // hist blocks per channel
constexpr int APC    = 16;             // apply blocks per channel
constexpr int NHIST  = CPG * HPC;      // 192 hist-role blocks
constexpr int NAPPLY = CPG * APC;      // 384 apply-role blocks
constexpr int NBLK   = NHIST + NAPPLY; // 576 <= 148*4 -> single co-resident wave

// Scratch — __device__ globals (zero at load; cleanup kernel re-zeroes per replay)
__device__ int g_hist[NCH * NB];
__device__ int g_ctr [GROUPS];

// ---------------------------------------------------------------------------
// Fused persistent kernel: role-specialized producer/consumer pipeline.
// hist blocks (read-bound) and apply blocks (write-bound) co-run, overlapping
// DRAM read and write streams that were previously serialized.
// ---------------------------------------------------------------------------
__global__ void __launch_bounds__(256, 4) fused_kernel(const float* __restrict__ in,
                                                       float* __restrict__ out) {
    __shared__ int sh[8 * NB];     // hist: 8 per-warp hists. apply: H/CS/RED/LUT.
    const int tid = threadIdx.x;
    const int bid = blockIdx.x;

    if (bid < NHIST) {
        // ---------------- HIST ROLE ----------------
        const int cg = bid / HPC;          // channel within group
        const int h  = bid % HPC;          // slice within channel
        int* const myh = &sh[(tid >> 5) * NB];

        for (int g = 0; g < GROUPS; g++) {
            const int c = g * CPG + cg;
            for (int i = tid; i < 8 * NB; i += 256) sh[i] = 0;
            __syncthreads();

            const float4* bi =
                reinterpret_cast<const float4*>(in + (size_t)c * P) + h * (P / 4 / HPC);
            for (int i = tid; i < P / 4 / HPC; i += 512) {   // 8192 float4 / slice
                float4 a = bi[i];
                float4 b = bi[i + 256];
                atomicAdd(&myh[(int)a.x], 1);
                atomicAdd(&myh[(int)a.y], 1);
                atomicAdd(&myh[(int)a.z], 1);
                atomicAdd(&myh[(int)a.w], 1);
                atomicAdd(&myh[(int)b.x], 1);
                atomicAdd(&myh[(int)b.y], 1);
                atomicAdd(&myh[(int)b.z], 1);
                atomicAdd(&myh[(int)b.w], 1);
            }
            __syncthreads();

            int s = 0;
#pragma unroll
            for (int k = 0; k < 8; k++) s += sh[k * NB + tid];
            if (s) atomicAdd(&g_hist[c * NB + tid], s);

            __threadfence();               // release my hist contributions
            __syncthreads();               // all threads' atomics+fences done
            if (tid == 0) atomicAdd(&g_ctr[g], 1);
        }
    } else {
        // ---------------- APPLY ROLE ----------------
        const int a  = bid - NHIST;
        const int cg = a / APC;            // channel within group
        const int j  = a % APC;            // slice within channel
        int*   H   = sh;
        int*   CS  = sh + NB;
        int*   RED = sh + 2 * NB;
        float* LUT = reinterpret_cast<float*>(sh + 3 * NB);

        for (int g = 0; g < GROUPS; g++) {
            const int c = g * CPG + cg;

            // Wait until all hist blocks of this group have published.
            if (tid == 0) {
                while (*(volatile int*)&g_ctr[g] < NHIST) __nanosleep(128);
            }
            __syncthreads();
            __threadfence();

            // Build this channel's LUT locally (exact PIL integer math).
            const int hv = __ldcg(&g_hist[c * NB + tid]);
            H[tid]  = hv;
            CS[tid] = hv;
            __syncthreads();
#pragma unroll
            for (int off = 1; off < NB; off <<= 1) {       // inclusive scan
                int v = (tid >= off) ? CS[tid - off] : 0;
                __syncthreads();
                CS[tid] += v;
                __syncthreads();
            }
            RED[tid] = hv ? tid : -1;                      // last nonzero bin
            __syncthreads();
#pragma unroll
            for (int sdx = 128; sdx > 0; sdx >>= 1) {
                if (tid < sdx) RED[tid] = max(RED[tid], RED[tid + sdx]);
                __syncthreads();
            }
            const int last_val = H[RED[0]];
            const int step = (P - last_val) / 255;
            const int safe = step > 0 ? step : 1;
            const int prev = tid ? CS[tid - 1] : 0;
            int lv = (prev + step / 2) / safe;
            lv = min(max(lv, 0), 255);
            if (step == 0) lv = tid;       // passthrough as identity LUT
            LUT[tid] = (float)lv;
            __syncthreads();

            // Apply this block's slice: 4096 float4, 2 loads in flight.
            const float4* bi =
                reinterpret_cast<const float4*>(in + (size_t)c * P) + j * (P / 4 / APC);
            float4* bo =
                reinterpret_cast<float4*>(out + (size_t)c * P) + j * (P / 4 / APC);
            for (int i = tid; i < P / 4 / APC; i += 512) {
                float4 x = bi[i];
                float4 y = bi[i + 256];
                float4 ox, oy;
                ox.x = LUT[(int)x.x]; ox.y = LUT[(int)x.y];
                ox.z = LUT[(int)x.z]; ox.w = LUT[(int)x.w];
                oy.x = LUT[(int)y.x]; oy.y = LUT[(int)y.y];
                oy.z = LUT[(int)y.z]; oy.w = LUT[(int)y.w];
                __stcs(&bo[i], ox);            // evict-first writes: protect L2
                __stcs(&bo[i + 256], oy);      // residency of upcoming input
            }
            __syncthreads();                    // smem reuse next group
        }
    }
}

// ---------------------------------------------------------------------------
// Cleanup: restore pristine scratch state so the next graph replay is clean.
// ---------------------------------------------------------------------------
__global__ void cleanup_kernel() {
    g_hist[blockIdx.x * NB + threadIdx.x] = 0;
    if (blockIdx.x == 0 && threadIdx.x < GROUPS) g_ctr[threadIdx.x] = 0;
}

// ---------------------------------------------------------------------------
extern "C" void kernel_launch(void* const* d_in, const int* in_sizes, int n_in,
                              void* d_out, int out_size) {
    const float* img = (const float*)d_in[0];
    float* out = (float*)d_out;

    fused_kernel<<<NBLK, 256>>>(img, out);
    cleanup_kernel<<<NCH, NB>>>();
}